// round 6
// baseline (speedup 1.0000x reference)
#include <cuda_runtime.h>
#include <cuda_bf16.h>
#include <cstdint>
#include <cstddef>

// ---------------------------------------------------------------------------
// Problem constants
// ---------------------------------------------------------------------------
#define B_SZ   2
#define S_SZ   4096
#define HID    2048
#define NH     32
#define HD     64
#define NHD    2048
#define M_ROWS (B_SZ * S_SZ)       // 8192
#define NT     32
#define NKV    4
#define SCALE_F 0.125f
#define KDIM   2048

// ---------------------------------------------------------------------------
// PTX helpers (plain sm_80+ features only)
// ---------------------------------------------------------------------------
__device__ __forceinline__ uint32_t smem_u32(const void* p) {
    uint32_t a;
    asm("{ .reg .u64 t; cvta.to.shared.u64 t, %1; cvt.u32.u64 %0, t; }" : "=r"(a) : "l"(p));
    return a;
}
#define CP_ASYNC16(dst, src) \
    asm volatile("cp.async.cg.shared.global [%0], [%1], 16;" :: "r"(dst), "l"(src) : "memory")
#define CP_COMMIT()  asm volatile("cp.async.commit_group;" ::: "memory")
#define CP_WAIT(n)   asm volatile("cp.async.wait_group %0;" :: "n"(n) : "memory")

__device__ __forceinline__ void ldm4(uint32_t* r, uint32_t addr) {
    asm volatile("ldmatrix.sync.aligned.m8n8.x4.shared.b16 {%0,%1,%2,%3}, [%4];"
        : "=r"(r[0]), "=r"(r[1]), "=r"(r[2]), "=r"(r[3]) : "r"(addr));
}
__device__ __forceinline__ void ldm4t(uint32_t* r, uint32_t addr) {
    asm volatile("ldmatrix.sync.aligned.m8n8.x4.trans.shared.b16 {%0,%1,%2,%3}, [%4];"
        : "=r"(r[0]), "=r"(r[1]), "=r"(r[2]), "=r"(r[3]) : "r"(addr));
}
__device__ __forceinline__ void mma_bf16(float* d, const uint32_t* a, uint32_t b0, uint32_t b1) {
    asm volatile("mma.sync.aligned.m16n8k16.row.col.f32.bf16.bf16.f32 "
        "{%0,%1,%2,%3}, {%4,%5,%6,%7}, {%8,%9}, {%0,%1,%2,%3};"
        : "+f"(d[0]), "+f"(d[1]), "+f"(d[2]), "+f"(d[3])
        : "r"(a[0]), "r"(a[1]), "r"(a[2]), "r"(a[3]), "r"(b0), "r"(b1));
}
__device__ __forceinline__ uint32_t pkbf(float a, float b) {
    __nv_bfloat162 t(__float2bfloat16(a), __float2bfloat16(b));
    return *(uint32_t*)&t;
}

// ---------------------------------------------------------------------------
// Scratch (device globals)
// ---------------------------------------------------------------------------
__device__ __nv_bfloat16 g_hshi[M_ROWS * HID];
__device__ __nv_bfloat16 g_hslo[M_ROWS * HID];
__device__ __nv_bfloat16 g_wthi[4 * HID * NHD];
__device__ __nv_bfloat16 g_wtlo[4 * HID * NHD];
__device__ __nv_bfloat16 g_qhi[M_ROWS * NHD];
__device__ __nv_bfloat16 g_qlo[M_ROWS * NHD];
__device__ __nv_bfloat16 g_khi[M_ROWS * NHD];
__device__ __nv_bfloat16 g_klo[M_ROWS * NHD];
__device__ __nv_bfloat16 g_vhi[M_ROWS * NHD];
__device__ __nv_bfloat16 g_vlo[M_ROWS * NHD];
__device__ __nv_bfloat16 g_atthi[M_ROWS * NHD];
__device__ __nv_bfloat16 g_attlo[M_ROWS * NHD];

// ---------------------------------------------------------------------------
// Pre-pass 1: elementwise fp32 -> (hi, lo) bf16 split
// ---------------------------------------------------------------------------
__global__ void split_kernel(const float* __restrict__ x,
                             __nv_bfloat16* __restrict__ hi,
                             __nv_bfloat16* __restrict__ lo, int n4)
{
    int i = blockIdx.x * blockDim.x + threadIdx.x;
    if (i >= n4) return;
    const float4 v = ((const float4*)x)[i];
    __nv_bfloat16 h0 = __float2bfloat16(v.x), h1 = __float2bfloat16(v.y);
    __nv_bfloat16 h2 = __float2bfloat16(v.z), h3 = __float2bfloat16(v.w);
    __nv_bfloat16 l0 = __float2bfloat16(v.x - __bfloat162float(h0));
    __nv_bfloat16 l1 = __float2bfloat16(v.y - __bfloat162float(h1));
    __nv_bfloat16 l2 = __float2bfloat16(v.z - __bfloat162float(h2));
    __nv_bfloat16 l3 = __float2bfloat16(v.w - __bfloat162float(h3));
    ((__nv_bfloat162*)hi)[i * 2]     = __nv_bfloat162(h0, h1);
    ((__nv_bfloat162*)hi)[i * 2 + 1] = __nv_bfloat162(h2, h3);
    ((__nv_bfloat162*)lo)[i * 2]     = __nv_bfloat162(l0, l1);
    ((__nv_bfloat162*)lo)[i * 2 + 1] = __nv_bfloat162(l2, l3);
}

// ---------------------------------------------------------------------------
// Pre-pass 2: W[K,N] -> Wt[N,K] with bf16 hi/lo split
// ---------------------------------------------------------------------------
__global__ void wsplit_kernel(const float* __restrict__ W0, const float* __restrict__ W1,
                              const float* __restrict__ W2, const float* __restrict__ W3,
                              __nv_bfloat16* __restrict__ hi, __nv_bfloat16* __restrict__ lo)
{
    const int z = blockIdx.z;
    const float* W = (z == 0) ? W0 : (z == 1) ? W1 : (z == 2) ? W2 : W3;
    __shared__ float t[32][33];
    const int n0 = blockIdx.x * 32, k0 = blockIdx.y * 32;
    const int tx = threadIdx.x, ty = threadIdx.y;
#pragma unroll
    for (int i = 0; i < 4; i++)
        t[ty + 8 * i][tx] = W[(size_t)(k0 + ty + 8 * i) * NHD + n0 + tx];
    __syncthreads();
    const size_t zo = (size_t)z * HID * NHD;
#pragma unroll
    for (int i = 0; i < 4; i++) {
        const float x = t[tx][ty + 8 * i];
        const __nv_bfloat16 h = __float2bfloat16(x);
        const __nv_bfloat16 l = __float2bfloat16(x - __bfloat162float(h));
        const size_t o = zo + (size_t)(n0 + ty + 8 * i) * KDIM + k0 + tx;
        hi[o] = h;
        lo[o] = l;
    }
}

// ---------------------------------------------------------------------------
// Split-bf16 HMMA GEMM: CTA tile 128(M) x 256(N), warp tile 64x64 (2x4 warps),
// BK=32, 2-stage cp.async double buffer. 6 MMA per ldmatrix.x4.
// ---------------------------------------------------------------------------
#define BK        32
#define NITER     (KDIM / BK)           // 64
#define STR_B     80
#define A_MAT_B   (128 * STR_B)         // 10240
#define B_MAT_B   (256 * STR_B)         // 20480
#define OFF_AH    0
#define OFF_AL    A_MAT_B
#define OFF_BH    (2 * A_MAT_B)
#define OFF_BL    (2 * A_MAT_B + B_MAT_B)
#define STAGE_B   (2 * A_MAT_B + 2 * B_MAT_B)   // 61440
#define GEMM_SMEM (2 * STAGE_B)                 // 122880

struct GemmPtrs {
    const __nv_bfloat16 *Ahi, *Alo, *Bhi, *Blo;
    float* C;
    __nv_bfloat16 *Chi, *Clo;
};

__device__ __forceinline__ void gemm_copy_stage(
    uint32_t sdst, const GemmPtrs& g, int m0, int n0, int kb, int tid)
{
    // 3072 x 16B chunks: Ahi 512, Alo 512, Bhi 1024, Blo 1024
#pragma unroll
    for (int i = 0; i < 12; i++) {
        const int idx = tid + i * 256;
        const __nv_bfloat16* sp;
        uint32_t doff;
        if (idx < 1024) {
            const int sel = idx >> 9, rem = idx & 511;
            const int row = rem >> 2, c = rem & 3;
            sp = (sel ? g.Alo : g.Ahi) + (size_t)(m0 + row) * KDIM + kb + c * 8;
            doff = (sel ? OFF_AL : OFF_AH) + (uint32_t)(row * STR_B + c * 16);
        } else {
            const int sel = (idx - 1024) >> 10, rem = (idx - 1024) & 1023;
            const int row = rem >> 2, c = rem & 3;
            sp = (sel ? g.Blo : g.Bhi) + (size_t)(n0 + row) * KDIM + kb + c * 8;
            doff = (sel ? OFF_BL : OFF_BH) + (uint32_t)(row * STR_B + c * 16);
        }
        CP_ASYNC16(sdst + doff, sp);
    }
    CP_COMMIT();
}

template <bool SPLIT>
__device__ __forceinline__ void gemm_body_mma(const GemmPtrs& g)
{
    extern __shared__ __align__(128) char smem[];
    const uint32_t sbase = smem_u32(smem);
    const int tid = threadIdx.x, wid = tid >> 5, lane = tid & 31;
    const int m0 = blockIdx.y * 128, n0 = blockIdx.x * 256;
    const int wm = wid & 1, wn = wid >> 1;      // warp tile: rows wm*64, cols wn*64

    float acc[4][8][4];
#pragma unroll
    for (int a = 0; a < 4; a++)
#pragma unroll
        for (int b = 0; b < 8; b++)
#pragma unroll
            for (int c = 0; c < 4; c++) acc[a][b][c] = 0.f;

    const uint32_t lofs = (uint32_t)((lane & 15) * STR_B + (lane >> 4) * 16);

    gemm_copy_stage(sbase, g, m0, n0, 0, tid);

    for (int t = 0; t < NITER; ++t) {
        if (t + 1 < NITER) {
            gemm_copy_stage(sbase + ((t + 1) & 1) * STAGE_B, g, m0, n0, (t + 1) * BK, tid);
            CP_WAIT(1);
        } else {
            CP_WAIT(0);
        }
        __syncthreads();

        const uint32_t s0 = sbase + (t & 1) * STAGE_B;
#pragma unroll
        for (int ks = 0; ks < 2; ++ks) {
            const uint32_t aoff = s0 + OFF_AH + (uint32_t)(wm * 64 * STR_B + ks * 32) + lofs;
            uint32_t Ah[16], Al[16];
#pragma unroll
            for (int mf = 0; mf < 4; mf++) {
                ldm4(Ah + mf * 4, aoff + mf * 16 * STR_B);
                ldm4(Al + mf * 4, aoff + (OFF_AL - OFF_AH) + mf * 16 * STR_B);
            }
#pragma unroll
            for (int half = 0; half < 2; half++) {
                const uint32_t boff = s0 + OFF_BH +
                    (uint32_t)((wn * 64 + half * 32) * STR_B + ks * 32) + lofs;
                uint32_t Bh[8], Bl[8];
                ldm4(Bh + 0, boff);
                ldm4(Bh + 4, boff + 16 * STR_B);
                ldm4(Bl + 0, boff + (OFF_BL - OFF_BH));
                ldm4(Bl + 4, boff + (OFF_BL - OFF_BH) + 16 * STR_B);
#pragma unroll
                for (int mf = 0; mf < 4; mf++)
#pragma unroll
                    for (int nl = 0; nl < 4; nl++) {
                        float* d = acc[mf][half * 4 + nl];
                        const uint32_t b0i = (nl >> 1) * 4 + (nl & 1);
                        mma_bf16(d, Ah + mf * 4, Bh[b0i], Bh[b0i + 2]);
                        mma_bf16(d, Ah + mf * 4, Bl[b0i], Bl[b0i + 2]);
                        mma_bf16(d, Al + mf * 4, Bh[b0i], Bh[b0i + 2]);
                    }
            }
        }
        __syncthreads();
    }

    const int gq = lane >> 2, tig = lane & 3;
#pragma unroll
    for (int mf = 0; mf < 4; mf++) {
        const int row = m0 + wm * 64 + mf * 16 + gq;
#pragma unroll
        for (int nf = 0; nf < 8; nf++) {
            const int col = n0 + wn * 64 + nf * 8 + tig * 2;
            if (SPLIT) {
#pragma unroll
                for (int half = 0; half < 2; half++) {
                    const size_t off = (size_t)(row + half * 8) * 2048 + col;
                    const float x0 = acc[mf][nf][half * 2], x1 = acc[mf][nf][half * 2 + 1];
                    const __nv_bfloat16 h0 = __float2bfloat16(x0), h1 = __float2bfloat16(x1);
                    const __nv_bfloat16 l0 = __float2bfloat16(x0 - __bfloat162float(h0));
                    const __nv_bfloat16 l1 = __float2bfloat16(x1 - __bfloat162float(h1));
                    *(__nv_bfloat162*)&g.Chi[off] = __nv_bfloat162(h0, h1);
                    *(__nv_bfloat162*)&g.Clo[off] = __nv_bfloat162(l0, l1);
                }
            } else {
                *(float2*)&g.C[(size_t)row * 2048 + col] =
                    make_float2(acc[mf][nf][0], acc[mf][nf][1]);
                *(float2*)&g.C[(size_t)(row + 8) * 2048 + col] =
                    make_float2(acc[mf][nf][2], acc[mf][nf][3]);
            }
        }
    }
}

__global__ __launch_bounds__(256, 1) void qkv_mma_kernel(
    const __nv_bfloat16* __restrict__ Ahi, const __nv_bfloat16* __restrict__ Alo,
    const __nv_bfloat16* __restrict__ Whi, const __nv_bfloat16* __restrict__ Wlo,
    __nv_bfloat16* __restrict__ Qh, __nv_bfloat16* __restrict__ Ql,
    __nv_bfloat16* __restrict__ Kh, __nv_bfloat16* __restrict__ Kl,
    __nv_bfloat16* __restrict__ Vh, __nv_bfloat16* __restrict__ Vl)
{
    const size_t WSZ = (size_t)HID * NHD;
    const int z = blockIdx.z;
    GemmPtrs g;
    g.Ahi = Ahi; g.Alo = Alo;
    g.Bhi = Whi + (size_t)z * WSZ; g.Blo = Wlo + (size_t)z * WSZ;
    g.C = nullptr;
    g.Chi = (z == 0) ? Qh : (z == 1) ? Kh : Vh;
    g.Clo = (z == 0) ? Ql : (z == 1) ? Kl : Vl;
    gemm_body_mma<true>(g);
}

__global__ __launch_bounds__(256, 1) void out_mma_kernel(
    const __nv_bfloat16* __restrict__ Ahi, const __nv_bfloat16* __restrict__ Alo,
    const __nv_bfloat16* __restrict__ Whi, const __nv_bfloat16* __restrict__ Wlo,
    float* __restrict__ C)
{
    GemmPtrs g;
    g.Ahi = Ahi; g.Alo = Alo; g.Bhi = Whi; g.Blo = Wlo;
    g.C = C; g.Chi = nullptr; g.Clo = nullptr;
    gemm_body_mma<false>(g);
}

// ---------------------------------------------------------------------------
// Tensor-core flash attention (split-bf16, 3 products), unchanged from R5.
// ---------------------------------------------------------------------------
#define ASTRB   144
#define AQH     0
#define AQL     18432
#define AKH     36864
#define AKL     55296
#define AVH     73728
#define AVL     92160
#define ATT_SMEM 110592

__device__ __forceinline__ int token_of(int tile, int jj)
{
    return ((tile >> 2) << 9) + ((jj >> 4) << 6) + ((tile & 3) << 4) + (jj & 15);
}

__global__ __launch_bounds__(256, 1) void attn_mma_kernel(
    const __nv_bfloat16* __restrict__ Qhi, const __nv_bfloat16* __restrict__ Qlo,
    const __nv_bfloat16* __restrict__ Khi, const __nv_bfloat16* __restrict__ Klo,
    const __nv_bfloat16* __restrict__ Vhi, const __nv_bfloat16* __restrict__ Vlo,
    __nv_bfloat16* __restrict__ Ohi, __nv_bfloat16* __restrict__ Olo)
{
    extern __shared__ __align__(128) char smem[];
    const uint32_t sbase = smem_u32(smem);
    const int t = blockIdx.x, h = blockIdx.y, b = blockIdx.z;
    const int tid = threadIdx.x, w = tid >> 5, lane = tid & 31;
    const size_t base = (size_t)b * S_SZ * NHD + (size_t)h * HD;

    const int tr = t >> 2, tc = t & 3;
    const int cr = min(max(tr, 1), 7);
    const int cc = min(max(tc, 1), 3);
    int kts[NKV];
    kts[0] = (cr - 1) * 4 + (cc - 1);
    kts[1] = (cr - 1) * 4 + cc;
    kts[2] = cr * 4 + (cc - 1);
    kts[3] = cr * 4 + cc;

    for (int i = tid; i < 2048; i += 256) {
        const int mat = i >> 10, rem = i & 1023;
        const int row = rem >> 3, c = rem & 7;
        const int qs = token_of(t, row);
        const __nv_bfloat16* src = (mat ? Qlo : Qhi) + base + (size_t)qs * NHD + c * 8;
        CP_ASYNC16(sbase + (mat ? AQL : AQH) + row * ASTRB + c * 16, src);
    }
    CP_COMMIT();
    CP_WAIT(0);
    __syncthreads();

    uint32_t qh[4][4], ql[4][4];
    const uint32_t qoff = (uint32_t)((w * 16 + (lane & 15)) * ASTRB + (lane >> 4) * 16);
#pragma unroll
    for (int kf = 0; kf < 4; kf++) {
        ldm4(qh[kf], sbase + AQH + qoff + kf * 32);
        ldm4(ql[kf], sbase + AQL + qoff + kf * 32);
    }

    float O[8][4];
#pragma unroll
    for (int nf = 0; nf < 8; nf++)
#pragma unroll
        for (int c = 0; c < 4; c++) O[nf][c] = 0.f;
    float m0 = -1e30f, m1 = -1e30f, l0 = 0.f, l1 = 0.f;

    for (int w4 = 0; w4 < NKV; ++w4) {
        const int kt = kts[w4];
        __syncthreads();
        for (int i = tid; i < 4096; i += 256) {
            const int mat = i >> 10, rem = i & 1023;
            const int row = rem >> 3, c = rem & 7;
            const int ks = token_of(kt, row);
            const size_t off = base + (size_t)ks * NHD + c * 8;
            const __nv_bfloat16* src =
                (mat == 0) ? Khi + off : (mat == 1) ? Klo + off :
                (mat == 2) ? Vhi + off : Vlo + off;
            const uint32_t doff = (mat == 0) ? AKH : (mat == 1) ? AKL :
                                  (mat == 2) ? AVH : AVL;
            CP_ASYNC16(sbase + doff + row * ASTRB + c * 16, src);
        }
        CP_COMMIT();
        CP_WAIT(0);
        __syncthreads();

        float S[16][4];
#pragma unroll
        for (int nf = 0; nf < 16; nf++)
#pragma unroll
            for (int c = 0; c < 4; c++) S[nf][c] = 0.f;

#pragma unroll
        for (int kf = 0; kf < 4; kf++) {
#pragma unroll
            for (int g = 0; g < 8; g++) {
                uint32_t kh[4], kl[4];
                const uint32_t ko = (uint32_t)((g * 16 + (lane & 15)) * ASTRB +
                                               (lane >> 4) * 16 + kf * 32);
                ldm4(kh, sbase + AKH + ko);
                mma_bf16(S[2 * g],     qh[kf], kh[0], kh[2]);
                mma_bf16(S[2 * g + 1], qh[kf], kh[1], kh[3]);
                ldm4(kl, sbase + AKL + ko);
                mma_bf16(S[2 * g],     qh[kf], kl[0], kl[2]);
                mma_bf16(S[2 * g + 1], qh[kf], kl[1], kl[3]);
                mma_bf16(S[2 * g],     ql[kf], kh[0], kh[2]);
                mma_bf16(S[2 * g + 1], ql[kf], kh[1], kh[3]);
            }
        }

        float tmax0 = -1e30f, tmax1 = -1e30f;
#pragma unroll
        for (int nf = 0; nf < 16; nf++) {
            S[nf][0] *= SCALE_F; S[nf][1] *= SCALE_F;
            S[nf][2] *= SCALE_F; S[nf][3] *= SCALE_F;
            tmax0 = fmaxf(tmax0, fmaxf(S[nf][0], S[nf][1]));
            tmax1 = fmaxf(tmax1, fmaxf(S[nf][2], S[nf][3]));
        }
        tmax0 = fmaxf(tmax0, __shfl_xor_sync(0xFFFFFFFF, tmax0, 1));
        tmax0 = fmaxf(tmax0, __shfl_xor_sync(0xFFFFFFFF, tmax0, 2));
        tmax1 = fmaxf(tmax1, __shfl_xor_sync(0xFFFFFFFF, tmax1, 1));
        tmax1 = fmaxf(tmax1, __shfl_xor_sync(0xFFFFFFFF, tmax1, 2));

        const float mn0 = fmaxf(m0, tmax0), mn1 = fmaxf(m1, tmax1);
        const float a0 = __expf(m0 - mn0), a1 = __expf(m1 - mn1);
        m0 = mn0; m1 = mn1;
        l0 *= a0; l1 *= a1;
#pragma unroll
        for (int nf = 0; nf < 8; nf++) {
            O[nf][0] *= a0; O[nf][1] *= a0;
            O[nf][2] *= a1; O[nf][3] *= a1;
        }
        float ls0 = 0.f, ls1 = 0.f;
#pragma unroll
        for (int nf = 0; nf < 16; nf++) {
            S[nf][0] = __expf(S[nf][0] - m0); ls0 += S[nf][0];
            S[nf][1] = __expf(S[nf][1] - m0); ls0 += S[nf][1];
            S[nf][2] = __expf(S[nf][2] - m1); ls1 += S[nf][2];
            S[nf][3] = __expf(S[nf][3] - m1); ls1 += S[nf][3];
        }
        l0 += ls0; l1 += ls1;

#pragma unroll
        for (int kf = 0; kf < 8; kf++) {
            uint32_t ph[4], pl[4];
            {
                const float* sA = S[2 * kf];
                const float* sB = S[2 * kf + 1];
                float hA0 = __bfloat162float(__float2bfloat16(sA[0]));
                float hA1 = __bfloat162float(__float2bfloat16(sA[1]));
                float hA2 = __bfloat162float(__float2bfloat16(sA[2]));
                float hA3 = __bfloat162float(__float2bfloat16(sA[3]));
                float hB0 = __bfloat162float(__float2bfloat16(sB[0]));
                float hB1 = __bfloat162float(__float2bfloat16(sB[1]));
                float hB2 = __bfloat162float(__float2bfloat16(sB[2]));
                float hB3 = __bfloat162float(__float2bfloat16(sB[3]));
                ph[0] = pkbf(sA[0], sA[1]); pl[0] = pkbf(sA[0] - hA0, sA[1] - hA1);
                ph[1] = pkbf(sA[2], sA[3]); pl[1] = pkbf(sA[2] - hA2, sA[3] - hA3);
                ph[2] = pkbf(sB[0], sB[1]); pl[2] = pkbf(sB[0] - hB0, sB[1] - hB1);
                ph[3] = pkbf(sB[2], sB[3]); pl[3] = pkbf(sB[2] - hB2, sB[3] - hB3);
            }
#pragma unroll
            for (int nv = 0; nv < 4; nv++) {
                uint32_t vh[4], vl[4];
                const uint32_t vo = (uint32_t)((kf * 16 + (lane & 15)) * ASTRB +
                                               (lane >> 4) * 16 + nv * 32);
                ldm4t(vh, sbase + AVH + vo);
                mma_bf16(O[2 * nv],     ph, vh[0], vh[1]);
                mma_bf16(O[2 * nv + 1], ph, vh[2], vh[3]);
                ldm4t(vl, sbase + AVL + vo);
                mma_bf16(O[2 * nv],     ph, vl[0], vl[1]);
                mma_bf16(O[2 * nv + 1], ph, vl[2], vl[3]);
                mma_bf16(O[2 * nv],     pl, vh[0], vh[1]);
                mma_bf16(O[2 * nv + 1], pl, vh[2], vh[3]);
            }
        }
    }

    l0 += __shfl_xor_sync(0xFFFFFFFF, l0, 1);
    l0 += __shfl_xor_sync(0xFFFFFFFF, l0, 2);
    l1 += __shfl_xor_sync(0xFFFFFFFF, l1, 1);
    l1 += __shfl_xor_sync(0xFFFFFFFF, l1, 2);
    const float inv0 = 1.f / l0, inv1 = 1.f / l1;
    const int gq = lane >> 2, tig = lane & 3;
    const int qs0 = token_of(t, w * 16 + gq);
    const int qs1 = token_of(t, w * 16 + gq + 8);
    const size_t r0 = base + (size_t)qs0 * NHD;
    const size_t r1 = base + (size_t)qs1 * NHD;
#pragma unroll
    for (int nf = 0; nf < 8; nf++) {
        const int col = nf * 8 + tig * 2;
        const float x0 = O[nf][0] * inv0, x1 = O[nf][1] * inv0;
        const float x2 = O[nf][2] * inv1, x3 = O[nf][3] * inv1;
        const __nv_bfloat16 h0 = __float2bfloat16(x0), h1 = __float2bfloat16(x1);
        const __nv_bfloat16 h2 = __float2bfloat16(x2), h3 = __float2bfloat16(x3);
        *(__nv_bfloat162*)&Ohi[r0 + col] = __nv_bfloat162(h0, h1);
        *(__nv_bfloat162*)&Ohi[r1 + col] = __nv_bfloat162(h2, h3);
        *(__nv_bfloat162*)&Olo[r0 + col] = __nv_bfloat162(
            __float2bfloat16(x0 - __bfloat162float(h0)),
            __float2bfloat16(x1 - __bfloat162float(h1)));
        *(__nv_bfloat162*)&Olo[r1 + col] = __nv_bfloat162(
            __float2bfloat16(x2 - __bfloat162float(h2)),
            __float2bfloat16(x3 - __bfloat162float(h3)));
    }
}

// ---------------------------------------------------------------------------
// Launch
// ---------------------------------------------------------------------------
extern "C" void kernel_launch(void* const* d_in, const int* in_sizes, int n_in,
                              void* d_out, int out_size)
{
    const float* hs = (const float*)d_in[0];
    const float* Wq = (const float*)d_in[1];
    const float* Wk = (const float*)d_in[2];
    const float* Wv = (const float*)d_in[3];
    const float* Wo = (const float*)d_in[4];
    float* out = (float*)d_out;

    __nv_bfloat16 *hshi, *hslo, *wthi, *wtlo;
    __nv_bfloat16 *qhi, *qlo, *khi, *klo, *vhi, *vlo, *atthi, *attlo;
    cudaGetSymbolAddress((void**)&hshi, g_hshi);
    cudaGetSymbolAddress((void**)&hslo, g_hslo);
    cudaGetSymbolAddress((void**)&wthi, g_wthi);
    cudaGetSymbolAddress((void**)&wtlo, g_wtlo);
    cudaGetSymbolAddress((void**)&qhi, g_qhi);
    cudaGetSymbolAddress((void**)&qlo, g_qlo);
    cudaGetSymbolAddress((void**)&khi, g_khi);
    cudaGetSymbolAddress((void**)&klo, g_klo);
    cudaGetSymbolAddress((void**)&vhi, g_vhi);
    cudaGetSymbolAddress((void**)&vlo, g_vlo);
    cudaGetSymbolAddress((void**)&atthi, g_atthi);
    cudaGetSymbolAddress((void**)&attlo, g_attlo);

    cudaFuncSetAttribute(qkv_mma_kernel, cudaFuncAttributeMaxDynamicSharedMemorySize, GEMM_SMEM);
    cudaFuncSetAttribute(out_mma_kernel, cudaFuncAttributeMaxDynamicSharedMemorySize, GEMM_SMEM);
    cudaFuncSetAttribute(attn_mma_kernel, cudaFuncAttributeMaxDynamicSharedMemorySize, ATT_SMEM);

    const int n4 = (M_ROWS * HID) / 4;
    split_kernel<<<(n4 + 255) / 256, 256>>>(hs, hshi, hslo, n4);
    wsplit_kernel<<<dim3(NHD / 32, HID / 32, 4), dim3(32, 8)>>>(Wq, Wk, Wv, Wo, wthi, wtlo);

    qkv_mma_kernel<<<dim3(NHD / 256, M_ROWS / 128, 3), 256, GEMM_SMEM>>>(
        hshi, hslo, wthi, wtlo, qhi, qlo, khi, klo, vhi, vlo);

    attn_mma_kernel<<<dim3(NT, NH, B_SZ), 256, ATT_SMEM>>>(
        qhi, qlo, khi, klo, vhi, vlo, atthi, attlo);

    const size_t WSZ = (size_t)HID * NHD;
    out_mma_kernel<<<dim3(HID / 256, M_ROWS / 128), 256, GEMM_SMEM>>>(
        atthi, attlo, wthi + 3 * WSZ, wtlo + 3 * WSZ, out);
}

// round 7
// speedup vs baseline: 1.1026x; 1.1026x over previous
#include <cuda_runtime.h>
#include <cuda_bf16.h>
#include <cstdint>
#include <cstddef>

// ---------------------------------------------------------------------------
// Problem constants
// ---------------------------------------------------------------------------
#define B_SZ   2
#define S_SZ   4096
#define HID    2048
#define NH     32
#define HD     64
#define NHD    2048
#define M_ROWS (B_SZ * S_SZ)       // 8192
#define NT     32
#define NKV    4
#define SCALE_F 0.125f
#define KDIM   2048

// ---------------------------------------------------------------------------
// PTX helpers (plain sm_80+ features only)
// ---------------------------------------------------------------------------
__device__ __forceinline__ uint32_t smem_u32(const void* p) {
    uint32_t a;
    asm("{ .reg .u64 t; cvta.to.shared.u64 t, %1; cvt.u32.u64 %0, t; }" : "=r"(a) : "l"(p));
    return a;
}
#define CP_ASYNC16(dst, src) \
    asm volatile("cp.async.cg.shared.global [%0], [%1], 16;" :: "r"(dst), "l"(src) : "memory")
#define CP_COMMIT()  asm volatile("cp.async.commit_group;" ::: "memory")
#define CP_WAIT(n)   asm volatile("cp.async.wait_group %0;" :: "n"(n) : "memory")

__device__ __forceinline__ void ldm4(uint32_t* r, uint32_t addr) {
    asm volatile("ldmatrix.sync.aligned.m8n8.x4.shared.b16 {%0,%1,%2,%3}, [%4];"
        : "=r"(r[0]), "=r"(r[1]), "=r"(r[2]), "=r"(r[3]) : "r"(addr));
}
__device__ __forceinline__ void ldm4t(uint32_t* r, uint32_t addr) {
    asm volatile("ldmatrix.sync.aligned.m8n8.x4.trans.shared.b16 {%0,%1,%2,%3}, [%4];"
        : "=r"(r[0]), "=r"(r[1]), "=r"(r[2]), "=r"(r[3]) : "r"(addr));
}
__device__ __forceinline__ void mma_bf16(float* d, const uint32_t* a, uint32_t b0, uint32_t b1) {
    asm volatile("mma.sync.aligned.m16n8k16.row.col.f32.bf16.bf16.f32 "
        "{%0,%1,%2,%3}, {%4,%5,%6,%7}, {%8,%9}, {%0,%1,%2,%3};"
        : "+f"(d[0]), "+f"(d[1]), "+f"(d[2]), "+f"(d[3])
        : "r"(a[0]), "r"(a[1]), "r"(a[2]), "r"(a[3]), "r"(b0), "r"(b1));
}
__device__ __forceinline__ uint32_t pkbf(float a, float b) {
    __nv_bfloat162 t(__float2bfloat16(a), __float2bfloat16(b));
    return *(uint32_t*)&t;
}

// ---------------------------------------------------------------------------
// Scratch (device globals)
// ---------------------------------------------------------------------------
__device__ __nv_bfloat16 g_hshi[M_ROWS * HID];
__device__ __nv_bfloat16 g_hslo[M_ROWS * HID];
__device__ __nv_bfloat16 g_wthi[4 * HID * NHD];
__device__ __nv_bfloat16 g_wtlo[4 * HID * NHD];
__device__ __nv_bfloat16 g_qhi[M_ROWS * NHD];
__device__ __nv_bfloat16 g_qlo[M_ROWS * NHD];
__device__ __nv_bfloat16 g_khi[M_ROWS * NHD];
__device__ __nv_bfloat16 g_klo[M_ROWS * NHD];
__device__ __nv_bfloat16 g_vhi[M_ROWS * NHD];
__device__ __nv_bfloat16 g_vlo[M_ROWS * NHD];
__device__ __nv_bfloat16 g_atthi[M_ROWS * NHD];
__device__ __nv_bfloat16 g_attlo[M_ROWS * NHD];

// ---------------------------------------------------------------------------
// Pre-pass 1: elementwise fp32 -> (hi, lo) bf16 split
// ---------------------------------------------------------------------------
__global__ void split_kernel(const float* __restrict__ x,
                             __nv_bfloat16* __restrict__ hi,
                             __nv_bfloat16* __restrict__ lo, int n4)
{
    int i = blockIdx.x * blockDim.x + threadIdx.x;
    if (i >= n4) return;
    const float4 v = ((const float4*)x)[i];
    __nv_bfloat16 h0 = __float2bfloat16(v.x), h1 = __float2bfloat16(v.y);
    __nv_bfloat16 h2 = __float2bfloat16(v.z), h3 = __float2bfloat16(v.w);
    __nv_bfloat16 l0 = __float2bfloat16(v.x - __bfloat162float(h0));
    __nv_bfloat16 l1 = __float2bfloat16(v.y - __bfloat162float(h1));
    __nv_bfloat16 l2 = __float2bfloat16(v.z - __bfloat162float(h2));
    __nv_bfloat16 l3 = __float2bfloat16(v.w - __bfloat162float(h3));
    ((__nv_bfloat162*)hi)[i * 2]     = __nv_bfloat162(h0, h1);
    ((__nv_bfloat162*)hi)[i * 2 + 1] = __nv_bfloat162(h2, h3);
    ((__nv_bfloat162*)lo)[i * 2]     = __nv_bfloat162(l0, l1);
    ((__nv_bfloat162*)lo)[i * 2 + 1] = __nv_bfloat162(l2, l3);
}

// ---------------------------------------------------------------------------
// Pre-pass 2: W[K,N] -> Wt[N,K] with bf16 hi/lo split
// ---------------------------------------------------------------------------
__global__ void wsplit_kernel(const float* __restrict__ W0, const float* __restrict__ W1,
                              const float* __restrict__ W2, const float* __restrict__ W3,
                              __nv_bfloat16* __restrict__ hi, __nv_bfloat16* __restrict__ lo)
{
    const int z = blockIdx.z;
    const float* W = (z == 0) ? W0 : (z == 1) ? W1 : (z == 2) ? W2 : W3;
    __shared__ float t[32][33];
    const int n0 = blockIdx.x * 32, k0 = blockIdx.y * 32;
    const int tx = threadIdx.x, ty = threadIdx.y;
#pragma unroll
    for (int i = 0; i < 4; i++)
        t[ty + 8 * i][tx] = W[(size_t)(k0 + ty + 8 * i) * NHD + n0 + tx];
    __syncthreads();
    const size_t zo = (size_t)z * HID * NHD;
#pragma unroll
    for (int i = 0; i < 4; i++) {
        const float x = t[tx][ty + 8 * i];
        const __nv_bfloat16 h = __float2bfloat16(x);
        const __nv_bfloat16 l = __float2bfloat16(x - __bfloat162float(h));
        const size_t o = zo + (size_t)(n0 + ty + 8 * i) * KDIM + k0 + tx;
        hi[o] = h;
        lo[o] = l;
    }
}

// ---------------------------------------------------------------------------
// Split-bf16 HMMA GEMM: CTA tile 128x128, 4 warps with 64x64 warp tiles
// (A hi+lo fragments resident per k-step: 16 ldm4 + 96 MMA per k16/warp),
// BK=32, 2-stage cp.async double buffer, 80KB smem -> 2 CTAs/SM.
// ---------------------------------------------------------------------------
#define BK        32
#define NITER     (KDIM / BK)           // 64
#define STR_B     80
#define MAT_B     (128 * STR_B)         // 10240
#define OFF_AH    0
#define OFF_AL    MAT_B
#define OFF_BH    (2 * MAT_B)
#define OFF_BL    (3 * MAT_B)
#define STAGE_B   (4 * MAT_B)           // 40960
#define GEMM_SMEM (2 * STAGE_B)         // 81920

struct GemmPtrs {
    const __nv_bfloat16 *Ahi, *Alo, *Bhi, *Blo;
    float* C;
    __nv_bfloat16 *Chi, *Clo;
};

__device__ __forceinline__ void gemm_copy_stage(
    uint32_t sdst, const GemmPtrs& g, int m0, int n0, int kb, int tid)
{
    // 2048 x 16B chunks: Ahi/Alo/Bhi/Blo 512 each; 128 threads x 16 iters
#pragma unroll
    for (int i = 0; i < 16; i++) {
        const int idx = tid + i * 128;
        const int mat = idx >> 9, rem = idx & 511;
        const int row = rem >> 2, c = rem & 3;
        const __nv_bfloat16* sp;
        if (mat == 0)      sp = g.Ahi + (size_t)(m0 + row) * KDIM + kb + c * 8;
        else if (mat == 1) sp = g.Alo + (size_t)(m0 + row) * KDIM + kb + c * 8;
        else if (mat == 2) sp = g.Bhi + (size_t)(n0 + row) * KDIM + kb + c * 8;
        else               sp = g.Blo + (size_t)(n0 + row) * KDIM + kb + c * 8;
        CP_ASYNC16(sdst + mat * MAT_B + row * STR_B + c * 16, sp);
    }
    CP_COMMIT();
}

template <bool SPLIT>
__device__ __forceinline__ void gemm_body_mma(const GemmPtrs& g)
{
    extern __shared__ __align__(128) char smem[];
    const uint32_t sbase = smem_u32(smem);
    const int tid = threadIdx.x, wid = tid >> 5, lane = tid & 31;
    const int m0 = blockIdx.y * 128, n0 = blockIdx.x * 128;
    const int wm = wid & 1, wn = wid >> 1;      // warp tile: rows wm*64, cols wn*64

    float acc[4][8][4];
#pragma unroll
    for (int a = 0; a < 4; a++)
#pragma unroll
        for (int b = 0; b < 8; b++)
#pragma unroll
            for (int c = 0; c < 4; c++) acc[a][b][c] = 0.f;

    const uint32_t lofs = (uint32_t)((lane & 15) * STR_B + (lane >> 4) * 16);

    gemm_copy_stage(sbase, g, m0, n0, 0, tid);

    for (int t = 0; t < NITER; ++t) {
        if (t + 1 < NITER) {
            gemm_copy_stage(sbase + ((t + 1) & 1) * STAGE_B, g, m0, n0, (t + 1) * BK, tid);
            CP_WAIT(1);
        } else {
            CP_WAIT(0);
        }
        __syncthreads();

        const uint32_t s0 = sbase + (t & 1) * STAGE_B;
#pragma unroll
        for (int ks = 0; ks < 2; ++ks) {
            const uint32_t aoff = s0 + OFF_AH + (uint32_t)(wm * 64 * STR_B + ks * 32) + lofs;
            uint32_t Ah[16], Al[16];
#pragma unroll
            for (int mf = 0; mf < 4; mf++) {
                ldm4(Ah + mf * 4, aoff + mf * 16 * STR_B);
                ldm4(Al + mf * 4, aoff + (OFF_AL - OFF_AH) + mf * 16 * STR_B);
            }
#pragma unroll
            for (int half = 0; half < 2; half++) {
                const uint32_t boff = s0 + OFF_BH +
                    (uint32_t)((wn * 64 + half * 32) * STR_B + ks * 32) + lofs;
                uint32_t Bh[8], Bl[8];
                ldm4(Bh + 0, boff);
                ldm4(Bh + 4, boff + 16 * STR_B);
                ldm4(Bl + 0, boff + (OFF_BL - OFF_BH));
                ldm4(Bl + 4, boff + (OFF_BL - OFF_BH) + 16 * STR_B);
#pragma unroll
                for (int mf = 0; mf < 4; mf++)
#pragma unroll
                    for (int nl = 0; nl < 4; nl++) {
                        float* d = acc[mf][half * 4 + nl];
                        const uint32_t b0i = (nl >> 1) * 4 + (nl & 1);
                        mma_bf16(d, Ah + mf * 4, Bh[b0i], Bh[b0i + 2]);
                        mma_bf16(d, Ah + mf * 4, Bl[b0i], Bl[b0i + 2]);
                        mma_bf16(d, Al + mf * 4, Bh[b0i], Bh[b0i + 2]);
                    }
            }
        }
        __syncthreads();
    }

    const int gq = lane >> 2, tig = lane & 3;
#pragma unroll
    for (int mf = 0; mf < 4; mf++) {
        const int row = m0 + wm * 64 + mf * 16 + gq;
#pragma unroll
        for (int nf = 0; nf < 8; nf++) {
            const int col = n0 + wn * 64 + nf * 8 + tig * 2;
            if (SPLIT) {
#pragma unroll
                for (int half = 0; half < 2; half++) {
                    const size_t off = (size_t)(row + half * 8) * 2048 + col;
                    const float x0 = acc[mf][nf][half * 2], x1 = acc[mf][nf][half * 2 + 1];
                    const __nv_bfloat16 h0 = __float2bfloat16(x0), h1 = __float2bfloat16(x1);
                    const __nv_bfloat16 l0 = __float2bfloat16(x0 - __bfloat162float(h0));
                    const __nv_bfloat16 l1 = __float2bfloat16(x1 - __bfloat162float(h1));
                    *(__nv_bfloat162*)&g.Chi[off] = __nv_bfloat162(h0, h1);
                    *(__nv_bfloat162*)&g.Clo[off] = __nv_bfloat162(l0, l1);
                }
            } else {
                *(float2*)&g.C[(size_t)row * 2048 + col] =
                    make_float2(acc[mf][nf][0], acc[mf][nf][1]);
                *(float2*)&g.C[(size_t)(row + 8) * 2048 + col] =
                    make_float2(acc[mf][nf][2], acc[mf][nf][3]);
            }
        }
    }
}

__global__ __launch_bounds__(128, 2) void qkv_mma_kernel(
    const __nv_bfloat16* __restrict__ Ahi, const __nv_bfloat16* __restrict__ Alo,
    const __nv_bfloat16* __restrict__ Whi, const __nv_bfloat16* __restrict__ Wlo,
    __nv_bfloat16* __restrict__ Qh, __nv_bfloat16* __restrict__ Ql,
    __nv_bfloat16* __restrict__ Kh, __nv_bfloat16* __restrict__ Kl,
    __nv_bfloat16* __restrict__ Vh, __nv_bfloat16* __restrict__ Vl)
{
    const size_t WSZ = (size_t)HID * NHD;
    const int z = blockIdx.z;
    GemmPtrs g;
    g.Ahi = Ahi; g.Alo = Alo;
    g.Bhi = Whi + (size_t)z * WSZ; g.Blo = Wlo + (size_t)z * WSZ;
    g.C = nullptr;
    g.Chi = (z == 0) ? Qh : (z == 1) ? Kh : Vh;
    g.Clo = (z == 0) ? Ql : (z == 1) ? Kl : Vl;
    gemm_body_mma<true>(g);
}

__global__ __launch_bounds__(128, 2) void out_mma_kernel(
    const __nv_bfloat16* __restrict__ Ahi, const __nv_bfloat16* __restrict__ Alo,
    const __nv_bfloat16* __restrict__ Whi, const __nv_bfloat16* __restrict__ Wlo,
    float* __restrict__ C)
{
    GemmPtrs g;
    g.Ahi = Ahi; g.Alo = Alo; g.Bhi = Whi; g.Blo = Wlo;
    g.C = C; g.Chi = nullptr; g.Clo = nullptr;
    gemm_body_mma<false>(g);
}

// ---------------------------------------------------------------------------
// Tensor-core flash attention (split-bf16, 3 products), unchanged from R5.
// ---------------------------------------------------------------------------
#define ASTRB   144
#define AQH     0
#define AQL     18432
#define AKH     36864
#define AKL     55296
#define AVH     73728
#define AVL     92160
#define ATT_SMEM 110592

__device__ __forceinline__ int token_of(int tile, int jj)
{
    return ((tile >> 2) << 9) + ((jj >> 4) << 6) + ((tile & 3) << 4) + (jj & 15);
}

__global__ __launch_bounds__(256, 1) void attn_mma_kernel(
    const __nv_bfloat16* __restrict__ Qhi, const __nv_bfloat16* __restrict__ Qlo,
    const __nv_bfloat16* __restrict__ Khi, const __nv_bfloat16* __restrict__ Klo,
    const __nv_bfloat16* __restrict__ Vhi, const __nv_bfloat16* __restrict__ Vlo,
    __nv_bfloat16* __restrict__ Ohi, __nv_bfloat16* __restrict__ Olo)
{
    extern __shared__ __align__(128) char smem[];
    const uint32_t sbase = smem_u32(smem);
    const int t = blockIdx.x, h = blockIdx.y, b = blockIdx.z;
    const int tid = threadIdx.x, w = tid >> 5, lane = tid & 31;
    const size_t base = (size_t)b * S_SZ * NHD + (size_t)h * HD;

    const int tr = t >> 2, tc = t & 3;
    const int cr = min(max(tr, 1), 7);
    const int cc = min(max(tc, 1), 3);
    int kts[NKV];
    kts[0] = (cr - 1) * 4 + (cc - 1);
    kts[1] = (cr - 1) * 4 + cc;
    kts[2] = cr * 4 + (cc - 1);
    kts[3] = cr * 4 + cc;

    for (int i = tid; i < 2048; i += 256) {
        const int mat = i >> 10, rem = i & 1023;
        const int row = rem >> 3, c = rem & 7;
        const int qs = token_of(t, row);
        const __nv_bfloat16* src = (mat ? Qlo : Qhi) + base + (size_t)qs * NHD + c * 8;
        CP_ASYNC16(sbase + (mat ? AQL : AQH) + row * ASTRB + c * 16, src);
    }
    CP_COMMIT();
    CP_WAIT(0);
    __syncthreads();

    uint32_t qh[4][4], ql[4][4];
    const uint32_t qoff = (uint32_t)((w * 16 + (lane & 15)) * ASTRB + (lane >> 4) * 16);
#pragma unroll
    for (int kf = 0; kf < 4; kf++) {
        ldm4(qh[kf], sbase + AQH + qoff + kf * 32);
        ldm4(ql[kf], sbase + AQL + qoff + kf * 32);
    }

    float O[8][4];
#pragma unroll
    for (int nf = 0; nf < 8; nf++)
#pragma unroll
        for (int c = 0; c < 4; c++) O[nf][c] = 0.f;
    float m0 = -1e30f, m1 = -1e30f, l0 = 0.f, l1 = 0.f;

    for (int w4 = 0; w4 < NKV; ++w4) {
        const int kt = kts[w4];
        __syncthreads();
        for (int i = tid; i < 4096; i += 256) {
            const int mat = i >> 10, rem = i & 1023;
            const int row = rem >> 3, c = rem & 7;
            const int ks = token_of(kt, row);
            const size_t off = base + (size_t)ks * NHD + c * 8;
            const __nv_bfloat16* src =
                (mat == 0) ? Khi + off : (mat == 1) ? Klo + off :
                (mat == 2) ? Vhi + off : Vlo + off;
            const uint32_t doff = (mat == 0) ? AKH : (mat == 1) ? AKL :
                                  (mat == 2) ? AVH : AVL;
            CP_ASYNC16(sbase + doff + row * ASTRB + c * 16, src);
        }
        CP_COMMIT();
        CP_WAIT(0);
        __syncthreads();

        float S[16][4];
#pragma unroll
        for (int nf = 0; nf < 16; nf++)
#pragma unroll
            for (int c = 0; c < 4; c++) S[nf][c] = 0.f;

#pragma unroll
        for (int kf = 0; kf < 4; kf++) {
#pragma unroll
            for (int g = 0; g < 8; g++) {
                uint32_t kh[4], kl[4];
                const uint32_t ko = (uint32_t)((g * 16 + (lane & 15)) * ASTRB +
                                               (lane >> 4) * 16 + kf * 32);
                ldm4(kh, sbase + AKH + ko);
                mma_bf16(S[2 * g],     qh[kf], kh[0], kh[2]);
                mma_bf16(S[2 * g + 1], qh[kf], kh[1], kh[3]);
                ldm4(kl, sbase + AKL + ko);
                mma_bf16(S[2 * g],     qh[kf], kl[0], kl[2]);
                mma_bf16(S[2 * g + 1], qh[kf], kl[1], kl[3]);
                mma_bf16(S[2 * g],     ql[kf], kh[0], kh[2]);
                mma_bf16(S[2 * g + 1], ql[kf], kh[1], kh[3]);
            }
        }

        float tmax0 = -1e30f, tmax1 = -1e30f;
#pragma unroll
        for (int nf = 0; nf < 16; nf++) {
            S[nf][0] *= SCALE_F; S[nf][1] *= SCALE_F;
            S[nf][2] *= SCALE_F; S[nf][3] *= SCALE_F;
            tmax0 = fmaxf(tmax0, fmaxf(S[nf][0], S[nf][1]));
            tmax1 = fmaxf(tmax1, fmaxf(S[nf][2], S[nf][3]));
        }
        tmax0 = fmaxf(tmax0, __shfl_xor_sync(0xFFFFFFFF, tmax0, 1));
        tmax0 = fmaxf(tmax0, __shfl_xor_sync(0xFFFFFFFF, tmax0, 2));
        tmax1 = fmaxf(tmax1, __shfl_xor_sync(0xFFFFFFFF, tmax1, 1));
        tmax1 = fmaxf(tmax1, __shfl_xor_sync(0xFFFFFFFF, tmax1, 2));

        const float mn0 = fmaxf(m0, tmax0), mn1 = fmaxf(m1, tmax1);
        const float a0 = __expf(m0 - mn0), a1 = __expf(m1 - mn1);
        m0 = mn0; m1 = mn1;
        l0 *= a0; l1 *= a1;
#pragma unroll
        for (int nf = 0; nf < 8; nf++) {
            O[nf][0] *= a0; O[nf][1] *= a0;
            O[nf][2] *= a1; O[nf][3] *= a1;
        }
        float ls0 = 0.f, ls1 = 0.f;
#pragma unroll
        for (int nf = 0; nf < 16; nf++) {
            S[nf][0] = __expf(S[nf][0] - m0); ls0 += S[nf][0];
            S[nf][1] = __expf(S[nf][1] - m0); ls0 += S[nf][1];
            S[nf][2] = __expf(S[nf][2] - m1); ls1 += S[nf][2];
            S[nf][3] = __expf(S[nf][3] - m1); ls1 += S[nf][3];
        }
        l0 += ls0; l1 += ls1;

#pragma unroll
        for (int kf = 0; kf < 8; kf++) {
            uint32_t ph[4], pl[4];
            {
                const float* sA = S[2 * kf];
                const float* sB = S[2 * kf + 1];
                float hA0 = __bfloat162float(__float2bfloat16(sA[0]));
                float hA1 = __bfloat162float(__float2bfloat16(sA[1]));
                float hA2 = __bfloat162float(__float2bfloat16(sA[2]));
                float hA3 = __bfloat162float(__float2bfloat16(sA[3]));
                float hB0 = __bfloat162float(__float2bfloat16(sB[0]));
                float hB1 = __bfloat162float(__float2bfloat16(sB[1]));
                float hB2 = __bfloat162float(__float2bfloat16(sB[2]));
                float hB3 = __bfloat162float(__float2bfloat16(sB[3]));
                ph[0] = pkbf(sA[0], sA[1]); pl[0] = pkbf(sA[0] - hA0, sA[1] - hA1);
                ph[1] = pkbf(sA[2], sA[3]); pl[1] = pkbf(sA[2] - hA2, sA[3] - hA3);
                ph[2] = pkbf(sB[0], sB[1]); pl[2] = pkbf(sB[0] - hB0, sB[1] - hB1);
                ph[3] = pkbf(sB[2], sB[3]); pl[3] = pkbf(sB[2] - hB2, sB[3] - hB3);
            }
#pragma unroll
            for (int nv = 0; nv < 4; nv++) {
                uint32_t vh[4], vl[4];
                const uint32_t vo = (uint32_t)((kf * 16 + (lane & 15)) * ASTRB +
                                               (lane >> 4) * 16 + nv * 32);
                ldm4t(vh, sbase + AVH + vo);
                mma_bf16(O[2 * nv],     ph, vh[0], vh[1]);
                mma_bf16(O[2 * nv + 1], ph, vh[2], vh[3]);
                ldm4t(vl, sbase + AVL + vo);
                mma_bf16(O[2 * nv],     ph, vl[0], vl[1]);
                mma_bf16(O[2 * nv + 1], ph, vl[2], vl[3]);
                mma_bf16(O[2 * nv],     pl, vh[0], vh[1]);
                mma_bf16(O[2 * nv + 1], pl, vh[2], vh[3]);
            }
        }
    }

    l0 += __shfl_xor_sync(0xFFFFFFFF, l0, 1);
    l0 += __shfl_xor_sync(0xFFFFFFFF, l0, 2);
    l1 += __shfl_xor_sync(0xFFFFFFFF, l1, 1);
    l1 += __shfl_xor_sync(0xFFFFFFFF, l1, 2);
    const float inv0 = 1.f / l0, inv1 = 1.f / l1;
    const int gq = lane >> 2, tig = lane & 3;
    const int qs0 = token_of(t, w * 16 + gq);
    const int qs1 = token_of(t, w * 16 + gq + 8);
    const size_t r0 = base + (size_t)qs0 * NHD;
    const size_t r1 = base + (size_t)qs1 * NHD;
#pragma unroll
    for (int nf = 0; nf < 8; nf++) {
        const int col = nf * 8 + tig * 2;
        const float x0 = O[nf][0] * inv0, x1 = O[nf][1] * inv0;
        const float x2 = O[nf][2] * inv1, x3 = O[nf][3] * inv1;
        const __nv_bfloat16 h0 = __float2bfloat16(x0), h1 = __float2bfloat16(x1);
        const __nv_bfloat16 h2 = __float2bfloat16(x2), h3 = __float2bfloat16(x3);
        *(__nv_bfloat162*)&Ohi[r0 + col] = __nv_bfloat162(h0, h1);
        *(__nv_bfloat162*)&Ohi[r1 + col] = __nv_bfloat162(h2, h3);
        *(__nv_bfloat162*)&Olo[r0 + col] = __nv_bfloat162(
            __float2bfloat16(x0 - __bfloat162float(h0)),
            __float2bfloat16(x1 - __bfloat162float(h1)));
        *(__nv_bfloat162*)&Olo[r1 + col] = __nv_bfloat162(
            __float2bfloat16(x2 - __bfloat162float(h2)),
            __float2bfloat16(x3 - __bfloat162float(h3)));
    }
}

// ---------------------------------------------------------------------------
// Launch
// ---------------------------------------------------------------------------
extern "C" void kernel_launch(void* const* d_in, const int* in_sizes, int n_in,
                              void* d_out, int out_size)
{
    const float* hs = (const float*)d_in[0];
    const float* Wq = (const float*)d_in[1];
    const float* Wk = (const float*)d_in[2];
    const float* Wv = (const float*)d_in[3];
    const float* Wo = (const float*)d_in[4];
    float* out = (float*)d_out;

    __nv_bfloat16 *hshi, *hslo, *wthi, *wtlo;
    __nv_bfloat16 *qhi, *qlo, *khi, *klo, *vhi, *vlo, *atthi, *attlo;
    cudaGetSymbolAddress((void**)&hshi, g_hshi);
    cudaGetSymbolAddress((void**)&hslo, g_hslo);
    cudaGetSymbolAddress((void**)&wthi, g_wthi);
    cudaGetSymbolAddress((void**)&wtlo, g_wtlo);
    cudaGetSymbolAddress((void**)&qhi, g_qhi);
    cudaGetSymbolAddress((void**)&qlo, g_qlo);
    cudaGetSymbolAddress((void**)&khi, g_khi);
    cudaGetSymbolAddress((void**)&klo, g_klo);
    cudaGetSymbolAddress((void**)&vhi, g_vhi);
    cudaGetSymbolAddress((void**)&vlo, g_vlo);
    cudaGetSymbolAddress((void**)&atthi, g_atthi);
    cudaGetSymbolAddress((void**)&attlo, g_attlo);

    cudaFuncSetAttribute(qkv_mma_kernel, cudaFuncAttributeMaxDynamicSharedMemorySize, GEMM_SMEM);
    cudaFuncSetAttribute(out_mma_kernel, cudaFuncAttributeMaxDynamicSharedMemorySize, GEMM_SMEM);
    cudaFuncSetAttribute(attn_mma_kernel, cudaFuncAttributeMaxDynamicSharedMemorySize, ATT_SMEM);

    const int n4 = (M_ROWS * HID) / 4;
    split_kernel<<<(n4 + 255) / 256, 256>>>(hs, hshi, hslo, n4);
    wsplit_kernel<<<dim3(NHD / 32, HID / 32, 4), dim3(32, 8)>>>(Wq, Wk, Wv, Wo, wthi, wtlo);

    qkv_mma_kernel<<<dim3(NHD / 128, M_ROWS / 128, 3), 128, GEMM_SMEM>>>(
        hshi, hslo, wthi, wtlo, qhi, qlo, khi, klo, vhi, vlo);

    attn_mma_kernel<<<dim3(NT, NH, B_SZ), 256, ATT_SMEM>>>(
        qhi, qlo, khi, klo, vhi, vlo, atthi, attlo);

    const size_t WSZ = (size_t)HID * NHD;
    out_mma_kernel<<<dim3(HID / 128, M_ROWS / 128), 128, GEMM_SMEM>>>(
        atthi, attlo, wthi + 3 * WSZ, wtlo + 3 * WSZ, out);
}